// round 3
// baseline (speedup 1.0000x reference)
#include <cuda_runtime.h>
#include <cstdint>

#define N_BINS 1000
#define EPS_F 1e-4f

// Persistent scratch: 3 x 1000 sigmoid table (no cudaMalloc allowed).
__device__ float g_S[3 * N_BINS];

// ---------------------------------------------------------------------------
// Kernel 1: build the 3x1000 sigmoid lookup table.
// S[j][b] = sigmoid((ub_j - logit(t_b)) / (ub_j - lb_j + eps))
// with (lb,ub) -> (min,max) swap as in get_parameters.
// Only 3000 evaluations -> precise logf/expf.
// ---------------------------------------------------------------------------
__global__ void pm_build_table(const float* __restrict__ bin_centers,
                               const float* __restrict__ lower_bounds,
                               const float* __restrict__ upper_bounds) {
    int i = blockIdx.x * blockDim.x + threadIdx.x;
    if (i >= 3 * N_BINS) return;
    int j = i / N_BINS;   // bound index 0..2
    int b = i % N_BINS;   // bin index
    float lbv = lower_bounds[j];
    float ubv = upper_bounds[j];
    float lo = fminf(lbv, ubv);
    float hi = fmaxf(lbv, ubv);
    float t = bin_centers[b];
    float g = logf(t / (1.0f - t));
    float x = (hi - g) / (hi - lo + EPS_F);
    g_S[i] = 1.0f / (1.0f + expf(-x));
}

// ---------------------------------------------------------------------------
// Kernel 2: streaming gather + product (int32 indices).
// Each thread handles TWO quads (8 rows) via two independent coalesced
// streams -> 6 outstanding LDG.128 per thread (MLP=6), overlapping the
// DRAM index stream with the smem gather work.
// Quad layout (3 x uint4 per quad of 4 rows):
//   v0 = [i0.a, i0.b, i0.c, i1.a]
//   v1 = [i1.b, i1.c, i2.a, i2.b]
//   v2 = [i2.c, i3.a, i3.b, i3.c]
// ---------------------------------------------------------------------------
__global__ void __launch_bounds__(256)
pm_eval_kernel(const uint4* __restrict__ idx_v, float4* __restrict__ out_v,
               int n_quads) {
    __shared__ float sS[3 * N_BINS];
    for (int i = threadIdx.x; i < 3 * N_BINS; i += blockDim.x)
        sS[i] = g_S[i];
    __syncthreads();

    const float* __restrict__ S0 = sS;
    const float* __restrict__ S1 = sS + N_BINS;
    const float* __restrict__ S2 = sS + 2 * N_BINS;

    int base = blockIdx.x * (blockDim.x * 2);
    int q0 = base + threadIdx.x;
    int q1 = q0 + blockDim.x;

    if (q1 < n_quads) {
        // Fast path: issue all 6 index loads up front (MLP=6).
        const uint4* p0 = idx_v + (size_t)q0 * 3;
        const uint4* p1 = idx_v + (size_t)q1 * 3;
        uint4 a0 = p0[0];
        uint4 a1 = p0[1];
        uint4 a2 = p0[2];
        uint4 b0 = p1[0];
        uint4 b1 = p1[1];
        uint4 b2 = p1[2];

        float4 oa, ob;
        oa.x = S0[a0.x] * S1[a0.y] * S2[a0.z];
        oa.y = S0[a0.w] * S1[a1.x] * S2[a1.y];
        oa.z = S0[a1.z] * S1[a1.w] * S2[a2.x];
        oa.w = S0[a2.y] * S1[a2.z] * S2[a2.w];

        ob.x = S0[b0.x] * S1[b0.y] * S2[b0.z];
        ob.y = S0[b0.w] * S1[b1.x] * S2[b1.y];
        ob.z = S0[b1.z] * S1[b1.w] * S2[b2.x];
        ob.w = S0[b2.y] * S1[b2.z] * S2[b2.w];

        out_v[q0] = oa;
        out_v[q1] = ob;
    } else if (q0 < n_quads) {
        const uint4* p0 = idx_v + (size_t)q0 * 3;
        uint4 a0 = p0[0];
        uint4 a1 = p0[1];
        uint4 a2 = p0[2];
        float4 oa;
        oa.x = S0[a0.x] * S1[a0.y] * S2[a0.z];
        oa.y = S0[a0.w] * S1[a1.x] * S2[a1.y];
        oa.z = S0[a1.z] * S1[a1.w] * S2[a2.x];
        oa.w = S0[a2.y] * S1[a2.z] * S2[a2.w];
        out_v[q0] = oa;
    }
}

// Scalar tail (only runs if out_size % 4 != 0; for this problem it won't).
__global__ void pm_eval_tail(const int* __restrict__ idx,
                             float* __restrict__ out, int start, int n) {
    int i = start + blockIdx.x * blockDim.x + threadIdx.x;
    if (i >= n) return;
    int a = idx[3 * (size_t)i + 0];
    int b = idx[3 * (size_t)i + 1];
    int c = idx[3 * (size_t)i + 2];
    out[i] = g_S[a] * g_S[N_BINS + b] * g_S[2 * N_BINS + c];
}

extern "C" void kernel_launch(void* const* d_in, const int* in_sizes, int n_in,
                              void* d_out, int out_size) {
    const float* bin_centers  = (const float*)d_in[0];
    const int*   obs_idx      = (const int*)d_in[1];   // JAX x64-off: int64 -> int32
    const float* lower_bounds = (const float*)d_in[2];
    const float* upper_bounds = (const float*)d_in[3];
    float* out = (float*)d_out;

    // 1) Build the 3000-entry sigmoid table.
    pm_build_table<<<(3 * N_BINS + 255) / 256, 256>>>(bin_centers, lower_bounds,
                                                      upper_bounds);

    // 2) Streaming gather-product, 8 rows (2 quads) per thread.
    int n = out_size;
    int n_quads = n / 4;
    if (n_quads > 0) {
        const int TPB = 256;
        int quads_per_block = TPB * 2;
        int blocks = (n_quads + quads_per_block - 1) / quads_per_block;
        pm_eval_kernel<<<blocks, TPB>>>((const uint4*)obs_idx, (float4*)out,
                                        n_quads);
    }
    int tail = n - n_quads * 4;
    if (tail > 0) {
        pm_eval_tail<<<1, 256>>>(obs_idx, out, n_quads * 4, n);
    }
}

// round 4
// speedup vs baseline: 1.0640x; 1.0640x over previous
#include <cuda_runtime.h>
#include <cstdint>

#define N_BINS 1000
#define EPS_F 1e-4f
#define TPB 256

// ---------------------------------------------------------------------------
// Fused kernel: per-block table build (3000 fast-math sigmoid evals) +
// software-pipelined streaming gather-product over int32 index quads.
//
// Quad layout (3 x uint4 per 4 rows of 3 int32 indices):
//   v0 = [i0.a, i0.b, i0.c, i1.a]
//   v1 = [i1.b, i1.c, i2.a, i2.b]
//   v2 = [i2.c, i3.a, i3.b, i3.c]
// ---------------------------------------------------------------------------
__global__ void __launch_bounds__(TPB)
pm_fused_kernel(const float* __restrict__ bin_centers,
                const float* __restrict__ lower_bounds,
                const float* __restrict__ upper_bounds,
                const uint4* __restrict__ idx_v,
                float4* __restrict__ out_v,
                const int* __restrict__ idx_s,   // scalar view for tail
                float* __restrict__ out_s,
                int n_quads, int n_rows) {
    __shared__ float sS[3 * N_BINS];

    // ---- table build: S[j][b] = sigmoid((ub_j - logit(t_b)) * inv_j) ----
    float hi[3], inv[3];
#pragma unroll
    for (int j = 0; j < 3; j++) {
        float l = lower_bounds[j];
        float u = upper_bounds[j];
        float lo = fminf(l, u);
        float h  = fmaxf(l, u);
        hi[j]  = h;
        inv[j] = 1.0f / (h - lo + EPS_F);
    }
    for (int b = threadIdx.x; b < N_BINS; b += TPB) {
        float t = __ldg(bin_centers + b);
        float g = __logf(t / (1.0f - t));
#pragma unroll
        for (int j = 0; j < 3; j++) {
            float x = (hi[j] - g) * inv[j];
            sS[j * N_BINS + b] = 1.0f / (1.0f + __expf(-x));
        }
    }
    __syncthreads();

    const float* __restrict__ S0 = sS;
    const float* __restrict__ S1 = sS + N_BINS;
    const float* __restrict__ S2 = sS + 2 * N_BINS;

    // ---- software-pipelined grid-stride loop over quads ----
    int stride = gridDim.x * TPB;
    int q = blockIdx.x * TPB + threadIdx.x;

    if (q < n_quads) {
        const uint4* p = idx_v + (size_t)q * 3;
        uint4 a0 = p[0];
        uint4 a1 = p[1];
        uint4 a2 = p[2];

        int qn = q + stride;
        while (qn < n_quads) {
            // Prefetch next quad's indices BEFORE computing current one,
            // so the DRAM stream overlaps the smem gather work.
            const uint4* pn = idx_v + (size_t)qn * 3;
            uint4 b0 = pn[0];
            uint4 b1 = pn[1];
            uint4 b2 = pn[2];

            float4 o;
            o.x = S0[a0.x] * S1[a0.y] * S2[a0.z];
            o.y = S0[a0.w] * S1[a1.x] * S2[a1.y];
            o.z = S0[a1.z] * S1[a1.w] * S2[a2.x];
            o.w = S0[a2.y] * S1[a2.z] * S2[a2.w];
            out_v[q] = o;

            a0 = b0; a1 = b1; a2 = b2;
            q = qn;
            qn += stride;
        }

        // Drain last quad.
        float4 o;
        o.x = S0[a0.x] * S1[a0.y] * S2[a0.z];
        o.y = S0[a0.w] * S1[a1.x] * S2[a1.y];
        o.z = S0[a1.z] * S1[a1.w] * S2[a2.x];
        o.w = S0[a2.y] * S1[a2.z] * S2[a2.w];
        out_v[q] = o;
    }

    // ---- scalar tail (n_rows % 4 != 0; never taken for this problem) ----
    int tail_start = n_quads * 4;
    if (blockIdx.x == 0) {
        int r = tail_start + threadIdx.x;
        if (r < n_rows) {
            int a = idx_s[3 * (size_t)r + 0];
            int b = idx_s[3 * (size_t)r + 1];
            int c = idx_s[3 * (size_t)r + 2];
            out_s[r] = S0[a] * S1[b] * S2[c];
        }
    }
}

extern "C" void kernel_launch(void* const* d_in, const int* in_sizes, int n_in,
                              void* d_out, int out_size) {
    const float* bin_centers  = (const float*)d_in[0];
    const int*   obs_idx      = (const int*)d_in[1];   // JAX x64-off: int64 -> int32
    const float* lower_bounds = (const float*)d_in[2];
    const float* upper_bounds = (const float*)d_in[3];
    float* out = (float*)d_out;

    int n = out_size;
    int n_quads = n / 4;

    // ~4 quads per thread -> steady-state pipelined loop, modest block count.
    int blocks = (n_quads + TPB - 1) / TPB;
    if (blocks > 2048) blocks = 2048;
    if (blocks < 1) blocks = 1;

    pm_fused_kernel<<<blocks, TPB>>>(bin_centers, lower_bounds, upper_bounds,
                                     (const uint4*)obs_idx, (float4*)out,
                                     obs_idx, out, n_quads, n);
}